// round 9
// baseline (speedup 1.0000x reference)
#include <cuda_runtime.h>
#include <cstdint>
#include <math.h>

#define CNUM   128
#define SMAX   401
#define KST    6
#define VALID  26
#define NW     8
#define NTH    (NW * 32)
#define NPAIR  (NW * VALID)
#define RING   32
#define MARGIN 24
#define PRO    26
#define NEGTOP (-(1 << 28))

// Scratch: softmax(y_pred) rows (64 MB).
__device__ float g_p[64 * 2000 * CNUM];

__global__ void softmax_kernel(const float* __restrict__ y, int rows) {
    int gw   = (blockIdx.x * blockDim.x + threadIdx.x) >> 5;
    int lane = threadIdx.x & 31;
    if (gw >= rows) return;
    float4 v = reinterpret_cast<const float4*>(y)[(size_t)gw * 32 + lane];
    float m = fmaxf(fmaxf(v.x, v.y), fmaxf(v.z, v.w));
#pragma unroll
    for (int o = 16; o; o >>= 1) m = fmaxf(m, __shfl_xor_sync(0xffffffffu, m, o));
    float e0 = __expf(v.x - m), e1 = __expf(v.y - m);
    float e2 = __expf(v.z - m), e3 = __expf(v.w - m);
    float sm = e0 + e1 + e2 + e3;
#pragma unroll
    for (int o = 16; o; o >>= 1) sm += __shfl_xor_sync(0xffffffffu, sm, o);
    float inv = __frcp_rn(sm);
    reinterpret_cast<float4*>(g_p)[(size_t)gw * 32 + lane] =
        make_float4(e0 * inv, e1 * inv, e2 * inv, e3 * inv);
}

// ---------------------------------------------------------------------------
// CTC alpha recursion, block-scaled registers, pipelined scale schedule.
// Lane owns pair p = 26w + lane - 6 (lanes 0..5 halo). Scale 2^ref fixed per
// 6-step block. refs for block k+1 are derived DURING block k from a 16-lane
// window max over start-of-block-k values (+ cross-warp suffix published one
// block earlier, folded into lanes 6..11) plus an own-decay extrapolation.
// Post-barrier critical path is just halo-LDS -> neighbor factor build.
// Inner step: 1 shuffle + 7 FMA-pipe ops (chain SHFL+FMUL+FFMA).
// ---------------------------------------------------------------------------
__device__ __forceinline__ void cp_async16(uint32_t saddr, const void* g) {
    asm volatile("cp.async.cg.shared.global [%0], [%1], 16;" :: "r"(saddr), "l"(g));
}
__device__ __forceinline__ float pw2c(int d) {
    return __int_as_float((min(max(d, -127), 127) + 127) << 23);
}

__global__ __launch_bounds__(NTH) void ctc_kernel(
    const int* __restrict__ labels, const int* __restrict__ in_len,
    const int* __restrict__ lab_len, float* __restrict__ out, int T, int L)
{
    __shared__ float s_y[RING][CNUM];
    __shared__ int4  s_pair[2][NPAIR];    // (mE bits, mL bits, ref, pad)
    __shared__ int   s_top[2][NW];        // per-warp suffix window max
    __shared__ int2  s_al[2 * NPAIR];

    const int b    = blockIdx.x;
    const int tid  = threadIdx.x;
    const int wid  = tid >> 5;
    const int lane = tid & 31;
    const float* pb = g_p + (size_t)b * T * CNUM;
    const int tend  = min(T, in_len[b]);

    const int p = wid * VALID + lane - KST;
    int  ext_c = CNUM - 1;
    bool skip  = false;
    if (p >= 0 && 2 * p + 1 < SMAX) {
        int v = labels[b * L + p];
        ext_c = (v < 0) ? 0 : v;
        if (p >= 1) {
            int v2 = labels[b * L + p - 1];
            v2 = (v2 < 0) ? 0 : v2;
            skip = (ext_c != v2);
        }
    }

    const bool loader = (wid == 0);
    uint32_t smy = (uint32_t)__cvta_generic_to_shared(&s_y[0][0]);

    if (loader) {
#pragma unroll
        for (int d = 0; d < PRO; ++d) {
            if (d < T) cp_async16(smy + (uint32_t)(d * CNUM + lane * 4) * 4,
                                  pb + (size_t)d * CNUM + lane * 4);
            asm volatile("cp.async.commit_group;");
        }
        asm volatile("cp.async.wait_group 19;");
    }
    __syncthreads();

    float mE = 0.f, mL = 0.f;
    int   ref = 0;
    if (p == 0) { mE = s_y[0][CNUM - 1]; mL = s_y[0][ext_c]; }

    if (lane >= VALID)
        s_pair[0][p] = make_int4(__float_as_int(mE), __float_as_int(mL), ref, 0);
    if (tid < NW) { s_top[0][tid] = NEGTOP; s_top[1][tid] = NEGTOP; }
    __syncthreads();

    int par = 0;
    int t0 = 1;
    for (; t0 + KST <= tend; t0 += KST, par ^= 1) {
        // ---- post-barrier: halo adopt (published values already rebased) ----
        if (lane < KST && p >= 0) {
            int4 h = s_pair[par][p];
            mE = __int_as_float(h.x); mL = __int_as_float(h.y); ref = h.z;
        }
        // ---- neighbor conversion factors (critical path) ----
        int r1 = __shfl_up_sync(0xffffffffu, ref, 1);
        int d  = r1 - ref;
        int dA = min(max(d, -127), 127);
        float fA = pw2c(dA), fB = pw2c(d - dA);
        float fBs = skip ? fB : 0.f;
        // ---- window tree on START-of-block values (overlaps with steps) ----
        int feS = max(__float_as_int(mE) >> 23, __float_as_int(mL) >> 23);
        int e_cur = ref + feS - 127;
        int wm = e_cur;
        wm = max(wm, __shfl_up_sync(0xffffffffu, wm, 1));
        wm = max(wm, __shfl_up_sync(0xffffffffu, wm, 2));
        wm = max(wm, __shfl_up_sync(0xffffffffu, wm, 4));
        wm = max(wm, __shfl_up_sync(0xffffffffu, wm, 8));   // 16-lane window
        int t31 = max(wm, __shfl_up_sync(0xffffffffu, wm, 2)); // lanes 14..31 @ lane 31
        int twi = (wid > 0) ? (wid - 1) : 0;
        int tw  = s_top[par][twi];
        if (wid > 0 && lane >= KST && lane <= 11) wm = max(wm, tw + 12);
        // ---- per-block constants ----
        float pyB[KST], pyL[KST], cB[KST], cL[KST];
#pragma unroll
        for (int j = 0; j < KST; ++j) {
            const float* row = s_y[(t0 + j) & (RING - 1)];
            pyB[j] = row[CNUM - 1];
            pyL[j] = row[ext_c];
            cB[j]  = fB  * pyB[j];
            cL[j]  = fBs * pyL[j];
        }
        // ---- 6 steps ----
#pragma unroll
        for (int j = 0; j < KST; ++j) {
            float m1 = __shfl_up_sync(0xffffffffu, mL, 1);
            float tE = m1 * fA;
            float nE = fmaf(tE, cB[j], mE * pyB[j]);
            mL = fmaf(tE, cL[j], (mL + mE) * pyL[j]);
            mE = nE;
        }
        // ---- end of block: own-decay extrapolated ref, rebase, publish ----
        int feE = max(__float_as_int(mE) >> 23, __float_as_int(mL) >> 23);
        int e_end = ref + feE - 127;
        int refNext = wm + MARGIN + (e_end - e_cur);
        int dd = ref - refNext;
        int ddA = min(max(dd, -127), 127);
        float gA = pw2c(ddA), gB = pw2c(dd - ddA);
        mE = (mE * gA) * gB;  mL = (mL * gA) * gB;
        ref = refNext;
        if (lane == 31) s_top[par ^ 1][wid] = t31;
        if (lane >= VALID)
            s_pair[par ^ 1][p] = make_int4(__float_as_int(mE), __float_as_int(mL), ref, 0);
        if (loader) {
#pragma unroll
            for (int jj = 0; jj < KST; ++jj) {
                int tn = t0 + PRO - 1 + jj;
                if (tn < T) cp_async16(smy + (uint32_t)((tn & (RING - 1)) * CNUM + lane * 4) * 4,
                                       pb + (size_t)tn * CNUM + lane * 4);
                asm volatile("cp.async.commit_group;");
            }
            asm volatile("cp.async.wait_group 19;");
        }
        __syncthreads();
    }

    // ---- tail (< 6 steps) ----
    if (t0 < tend) {
        if (lane < KST && p >= 0) {
            int4 h = s_pair[par][p];
            mE = __int_as_float(h.x); mL = __int_as_float(h.y); ref = h.z;
        }
        int r1 = __shfl_up_sync(0xffffffffu, ref, 1);
        int d  = r1 - ref;
        int dA = min(max(d, -127), 127);
        float fA = pw2c(dA), fB = pw2c(d - dA);
        float fBs = skip ? fB : 0.f;
        for (int t = t0; t < tend; ++t) {
            const float* row = s_y[t & (RING - 1)];
            float pB = row[CNUM - 1], pL = row[ext_c];
            float m1 = __shfl_up_sync(0xffffffffu, mL, 1);
            float tE = m1 * fA;
            float nE = fmaf(tE, fB * pB, mE * pB);
            mL = fmaf(tE, fBs * pL, (mL + mE) * pL);
            mE = nE;
        }
    }

    if (lane >= KST) {
        s_al[2 * p]     = make_int2(__float_as_int(mE), ref);
        s_al[2 * p + 1] = make_int2(__float_as_int(mL), ref);
    }
    __syncthreads();

    if (tid == 0) {
        int se = 2 * lab_len[b];
        int sp = (se > 0) ? (se - 1) : 0;
        int2 A = s_al[se];
        int2 P = s_al[sp];
        double va = (double)__int_as_float(A.x);
        double vp = (double)__int_as_float(P.x);
        long long ra = (va > 0.0) ? (long long)A.y : (long long)(-(1ll << 40));
        long long rp = (vp > 0.0) ? (long long)P.y : (long long)(-(1ll << 40));
        long long rm = (ra > rp) ? ra : rp;
        double sum = 0.0;
        if (va > 0.0) sum += va * exp2((double)(ra - rm));
        if (vp > 0.0) sum += vp * exp2((double)(rp - rm));
        out[b] = (float)(-(log(sum) + (double)rm * 0.6931471805599453));
    }
}

// ---------------------------------------------------------------------------
extern "C" void kernel_launch(void* const* d_in, const int* in_sizes, int n_in,
                              void* d_out, int out_size) {
    const float* y  = (const float*)d_in[0];
    const int*   yt = (const int*)d_in[1];
    const int*   il = (const int*)d_in[2];
    const int*   ll = (const int*)d_in[3];
    int B = in_sizes[2];
    int L = in_sizes[1] / B;
    int rows = in_sizes[0] / CNUM;   // B*T
    int T = rows / B;

    int sm_blocks = (rows * 32 + 255) / 256;
    softmax_kernel<<<sm_blocks, 256>>>(y, rows);
    ctc_kernel<<<B, NTH>>>(yt, il, ll, (float*)d_out, T, L);
}

// round 10
// speedup vs baseline: 1.4389x; 1.4389x over previous
#include <cuda_runtime.h>
#include <cstdint>
#include <math.h>

#define CNUM   128
#define SMAX   401
#define KST    6               // steps per barrier = halo lanes
#define VALID  26              // 32 - KST
#define NW     8               // 8*26 = 208 pairs >= 201
#define NTH    (NW * 32)       // 256
#define NPAIR  (NW * VALID)    // 208
#define RING   32
#define MARGIN 16
#define PRO    26              // prologue rows issued

// Scratch: softmax(y_pred) rows, [B][T][C] = 64*2000*128 floats (64 MB).
__device__ float g_p[64 * 2000 * CNUM];

// ---------------------------------------------------------------------------
// Kernel 1: row softmax over C=128. One warp per (b,t) row.
// ---------------------------------------------------------------------------
__global__ void softmax_kernel(const float* __restrict__ y, int rows) {
    int gw   = (blockIdx.x * blockDim.x + threadIdx.x) >> 5;
    int lane = threadIdx.x & 31;
    if (gw >= rows) return;
    float4 v = reinterpret_cast<const float4*>(y)[(size_t)gw * 32 + lane];
    float m = fmaxf(fmaxf(v.x, v.y), fmaxf(v.z, v.w));
#pragma unroll
    for (int o = 16; o; o >>= 1) m = fmaxf(m, __shfl_xor_sync(0xffffffffu, m, o));
    float e0 = __expf(v.x - m), e1 = __expf(v.y - m);
    float e2 = __expf(v.z - m), e3 = __expf(v.w - m);
    float sm = e0 + e1 + e2 + e3;
#pragma unroll
    for (int o = 16; o; o >>= 1) sm += __shfl_xor_sync(0xffffffffu, sm, o);
    float inv = __frcp_rn(sm);
    reinterpret_cast<float4*>(g_p)[(size_t)gw * 32 + lane] =
        make_float4(e0 * inv, e1 * inv, e2 * inv, e3 * inv);
}

// ---------------------------------------------------------------------------
// Kernel 2: CTC alpha recursion, block-scaled registers, tight 8-lane window
// (the R8 scheme: window on TRUE current values, used immediately).
// Lane owns pair p = 26w + lane - 6 (even 2p = blank, odd 2p+1 = label;
// lanes 0..5 = halo of prev warp). (mE, mL) raw floats at per-lane scale
// 2^ref, fixed for 6 steps. Boundary: halo adopt -> 8-lane window max ->
// rebase -> neighbor factors (+ per-block FMA constants). Inner step:
// 1 shuffle + FMA pipe, cross-lane chain SHFL+FMUL+FFMA = 34 cyc.
// Softmax rows stream through a 32-stage cp.async ring, distance 19 groups.
// ---------------------------------------------------------------------------
__device__ __forceinline__ void cp_async16(uint32_t saddr, const void* g) {
    asm volatile("cp.async.cg.shared.global [%0], [%1], 16;" :: "r"(saddr), "l"(g));
}
__device__ __forceinline__ float pw2c(int d) {   // exact 2^clamp(d,-127,127)
    return __int_as_float((min(max(d, -127), 127) + 127) << 23);
}

__global__ __launch_bounds__(NTH) void ctc_kernel(
    const int* __restrict__ labels, const int* __restrict__ in_len,
    const int* __restrict__ lab_len, float* __restrict__ out, int T, int L)
{
    __shared__ float s_y[RING][CNUM];     // 16 KB ring
    __shared__ int4  s_pair[2][NPAIR];    // (mE bits, mL bits, ref, pad)
    __shared__ int2  s_al[2 * NPAIR];     // final readout (m bits, ref)

    const int b    = blockIdx.x;
    const int tid  = threadIdx.x;
    const int wid  = tid >> 5;
    const int lane = tid & 31;
    const float* pb = g_p + (size_t)b * T * CNUM;
    const int tend  = min(T, in_len[b]);

    const int p = wid * VALID + lane - KST;
    int  ext_c = CNUM - 1;
    bool skip  = false;
    if (p >= 0 && 2 * p + 1 < SMAX) {
        int v = labels[b * L + p];
        ext_c = (v < 0) ? 0 : v;
        if (p >= 1) {
            int v2 = labels[b * L + p - 1];
            v2 = (v2 < 0) ? 0 : v2;
            skip = (ext_c != v2);
        }
    }

    const bool loader = (wid == 0);
    uint32_t smy = (uint32_t)__cvta_generic_to_shared(&s_y[0][0]);

    // Prologue: rows 0..25 issued; wait 19 -> rows 0..6 complete.
    if (loader) {
#pragma unroll
        for (int d = 0; d < PRO; ++d) {
            if (d < T) cp_async16(smy + (uint32_t)(d * CNUM + lane * 4) * 4,
                                  pb + (size_t)d * CNUM + lane * 4);
            asm volatile("cp.async.commit_group;");
        }
        asm volatile("cp.async.wait_group 19;");
    }
    __syncthreads();

    // t = 0 init
    float mE = 0.f, mL = 0.f;
    int   ref = 0;
    if (p == 0) { mE = s_y[0][CNUM - 1]; mL = s_y[0][ext_c]; }

    // pre-loop publish (parity 0)
    if (lane >= VALID)
        s_pair[0][p] = make_int4(__float_as_int(mE), __float_as_int(mL), ref, 0);
    __syncthreads();

    float fA = 1.f, fB = 1.f, fBs = 0.f;

    // boundary: halo refresh -> window max -> re-base -> factors
    auto boundary = [&](int par) {
        if (lane < KST && p >= 0) {
            int4 h = s_pair[par][p];
            mE = __int_as_float(h.x); mL = __int_as_float(h.y); ref = h.z;
        }
        int fe = __float_as_int(fmaxf(mE, mL)) >> 23;      // mE,mL >= 0
        int wm = ref + fe - 127;                           // current exponent
        wm = max(wm, __shfl_up_sync(0xffffffffu, wm, 1));
        wm = max(wm, __shfl_up_sync(0xffffffffu, wm, 2));
        wm = max(wm, __shfl_up_sync(0xffffffffu, wm, 4));  // 8-lane window
        int refNew = wm + MARGIN;
        int dd = ref - refNew;
        int ddA = min(max(dd, -127), 127);
        float gA = pw2c(ddA), gB = pw2c(dd - ddA);
        mE = (mE * gA) * gB;  mL = (mL * gA) * gB;
        ref = refNew;
        int r1 = __shfl_up_sync(0xffffffffu, ref, 1);
        int d  = r1 - ref;
        int dA = min(max(d, -127), 127);
        fA = pw2c(dA);  fB = pw2c(d - dA);
        fBs = skip ? fB : 0.f;
    };

    int par = 0;
    int t0 = 1;
    for (; t0 + KST <= tend; t0 += KST, par ^= 1) {
        boundary(par);
        float pyB[KST], pyL[KST], cB[KST], cL[KST];
#pragma unroll
        for (int j = 0; j < KST; ++j) {
            const float* row = s_y[(t0 + j) & (RING - 1)];
            pyB[j] = row[CNUM - 1];
            pyL[j] = row[ext_c];
            cB[j]  = fB  * pyB[j];
            cL[j]  = fBs * pyL[j];
        }
#pragma unroll
        for (int j = 0; j < KST; ++j) {
            float m1 = __shfl_up_sync(0xffffffffu, mL, 1);
            float tE = m1 * fA;
            float nE = fmaf(tE, cB[j], mE * pyB[j]);
            mL = fmaf(tE, cL[j], (mL + mE) * pyL[j]);
            mE = nE;
        }
        if (lane >= VALID)
            s_pair[par ^ 1][p] = make_int4(__float_as_int(mE), __float_as_int(mL), ref, 0);
        if (loader) {
#pragma unroll
            for (int jj = 0; jj < KST; ++jj) {
                int tn = t0 + PRO - 1 + jj;          // rows t0+25 .. t0+30
                if (tn < T) cp_async16(smy + (uint32_t)((tn & (RING - 1)) * CNUM + lane * 4) * 4,
                                       pb + (size_t)tn * CNUM + lane * 4);
                asm volatile("cp.async.commit_group;");
            }
            asm volatile("cp.async.wait_group 19;");
        }
        __syncthreads();
    }

    // tail (< 6 steps)
    if (t0 < tend) {
        boundary(par);
        for (int t = t0; t < tend; ++t) {
            const float* row = s_y[t & (RING - 1)];
            float pB = row[CNUM - 1], pL = row[ext_c];
            float m1 = __shfl_up_sync(0xffffffffu, mL, 1);
            float tE = m1 * fA;
            float nE = fmaf(tE, fB * pB, mE * pB);
            mL = fmaf(tE, fBs * pL, (mL + mE) * pL);
            mE = nE;
        }
    }

    // final publish (valid lanes)
    if (lane >= KST) {
        s_al[2 * p]     = make_int2(__float_as_int(mE), ref);
        s_al[2 * p + 1] = make_int2(__float_as_int(mL), ref);
    }
    __syncthreads();

    if (tid == 0) {
        int se = 2 * lab_len[b];
        int sp = (se > 0) ? (se - 1) : 0;
        int2 A = s_al[se];
        int2 P = s_al[sp];
        double va = (double)__int_as_float(A.x);
        double vp = (double)__int_as_float(P.x);
        long long ra = (va > 0.0) ? (long long)A.y : (long long)(-(1ll << 40));
        long long rp = (vp > 0.0) ? (long long)P.y : (long long)(-(1ll << 40));
        long long rm = (ra > rp) ? ra : rp;
        double sum = 0.0;
        if (va > 0.0) sum += va * exp2((double)(ra - rm));
        if (vp > 0.0) sum += vp * exp2((double)(rp - rm));
        out[b] = (float)(-(log(sum) + (double)rm * 0.6931471805599453));
    }
}

// ---------------------------------------------------------------------------
extern "C" void kernel_launch(void* const* d_in, const int* in_sizes, int n_in,
                              void* d_out, int out_size) {
    const float* y  = (const float*)d_in[0];
    const int*   yt = (const int*)d_in[1];
    const int*   il = (const int*)d_in[2];
    const int*   ll = (const int*)d_in[3];
    int B = in_sizes[2];
    int L = in_sizes[1] / B;
    int rows = in_sizes[0] / CNUM;   // B*T
    int T = rows / B;

    int sm_blocks = (rows * 32 + 255) / 256;
    softmax_kernel<<<sm_blocks, 256>>>(y, rows);
    ctc_kernel<<<B, NTH>>>(yt, il, ll, (float*)d_out, T, L);
}

// round 12
// speedup vs baseline: 1.7703x; 1.2303x over previous
#include <cuda_runtime.h>
#include <cstdint>
#include <math.h>

#define CNUM    128
#define SMAX    401
#define KST     8              // steps per barrier
#define HALO_L  4              // halo lanes (2 pairs each = 8 pairs = KST)
#define VALID_L 28
#define NW      4              // 4*28 lanes * 2 pairs = 224 pairs >= 202
#define NTH     (NW * 32)      // 128
#define NSLOT   (NW * VALID_L) // 112 slots (1 slot = 2 pairs = 4 states)
#define RING    64
#define MARGIN  20
#define PRO     26

// Scratch: softmax(y_pred) rows, [B][T][C] (64 MB).
__device__ float g_p[64 * 2000 * CNUM];

// ---------------------------------------------------------------------------
// Kernel 1: row softmax over C=128. One warp per (b,t) row.
// ---------------------------------------------------------------------------
__global__ void softmax_kernel(const float* __restrict__ y, int rows) {
    int gw   = (blockIdx.x * blockDim.x + threadIdx.x) >> 5;
    int lane = threadIdx.x & 31;
    if (gw >= rows) return;
    float4 v = reinterpret_cast<const float4*>(y)[(size_t)gw * 32 + lane];
    float m = fmaxf(fmaxf(v.x, v.y), fmaxf(v.z, v.w));
#pragma unroll
    for (int o = 16; o; o >>= 1) m = fmaxf(m, __shfl_xor_sync(0xffffffffu, m, o));
    float e0 = __expf(v.x - m), e1 = __expf(v.y - m);
    float e2 = __expf(v.z - m), e3 = __expf(v.w - m);
    float sm = e0 + e1 + e2 + e3;
#pragma unroll
    for (int o = 16; o; o >>= 1) sm += __shfl_xor_sync(0xffffffffu, sm, o);
    float inv = __frcp_rn(sm);
    reinterpret_cast<float4*>(g_p)[(size_t)gw * 32 + lane] =
        make_float4(e0 * inv, e1 * inv, e2 * inv, e3 * inv);
}

// ---------------------------------------------------------------------------
// Kernel 2: CTC alpha recursion, 2 pairs (4 states) per lane, block-scaled.
// Slot s = 28w + lane - 4 owns pairs (2s, 2s+1) = states 4s..4s+3
// (lanes 0..3 = halo mirroring prev warp's top 4 lanes; slot<0 stays zero).
// All 4 values share per-lane scale 2^ref, fixed for an 8-step block.
// Cross-lane: ONLY pair-0's inputs (prev lane's upper odd state) -> 1 SHFL
// per step; upper pair chains in-register => cross-lane dependence cycle
// spans 2 steps (shuffle latency half-hidden). Boundary per block: halo
// adopt -> 6-lane window max (24 states; flush-safe) -> rebase -> neighbor
// factor folded into per-block coefficients. cp.async ring 64 rows deep.
// ---------------------------------------------------------------------------
__device__ __forceinline__ void cp_async16(uint32_t saddr, const void* g) {
    asm volatile("cp.async.cg.shared.global [%0], [%1], 16;" :: "r"(saddr), "l"(g));
}
__device__ __forceinline__ float pw2c(int d) {   // exact 2^clamp(d,-127,127)
    return __int_as_float((min(max(d, -127), 127) + 127) << 23);
}

__global__ __launch_bounds__(NTH) void ctc_kernel(
    const int* __restrict__ labels, const int* __restrict__ in_len,
    const int* __restrict__ lab_len, float* __restrict__ out, int T, int L)
{
    __shared__ float s_y[RING][CNUM];     // 32 KB ring
    __shared__ int4  s_m[2][NSLOT];       // published mantissas (4 states)
    __shared__ int   s_r[2][NSLOT];       // published refs
    __shared__ int2  s_al[4 * NSLOT];     // final readout

    const int b    = blockIdx.x;
    const int tid  = threadIdx.x;
    const int wid  = tid >> 5;
    const int lane = tid & 31;
    const float* pb = g_p + (size_t)b * T * CNUM;
    const int tend  = min(T, in_len[b]);

    const int slot = wid * VALID_L + lane - HALO_L;
    const int q0 = 2 * slot, q1 = 2 * slot + 1;
    int  ext_ca = CNUM - 1, ext_cb = CNUM - 1;
    bool skipa = false, skipb = false;
    if (slot >= 0) {
        if (q0 < L) {
            int v = labels[b * L + q0];
            ext_ca = (v < 0) ? 0 : v;
            if (q0 >= 1) {
                int v2 = labels[b * L + q0 - 1];
                v2 = (v2 < 0) ? 0 : v2;
                skipa = (ext_ca != v2);
            }
        }
        if (q1 < L) {
            int v = labels[b * L + q1];
            ext_cb = (v < 0) ? 0 : v;
            int v2 = labels[b * L + q1 - 1];
            v2 = (v2 < 0) ? 0 : v2;
            skipb = (ext_cb != v2);
        }
    }
    const float skb = skipb ? 1.f : 0.f;

    const bool loader = (wid == 0);
    uint32_t smy = (uint32_t)__cvta_generic_to_shared(&s_y[0][0]);

    // Prologue: rows 0..25, one group each; wait 17 -> rows 0..8 complete.
    if (loader) {
#pragma unroll
        for (int d = 0; d < PRO; ++d) {
            if (d < T) cp_async16(smy + (uint32_t)(d * CNUM + lane * 4) * 4,
                                  pb + (size_t)d * CNUM + lane * 4);
            asm volatile("cp.async.commit_group;");
        }
        asm volatile("cp.async.wait_group 17;");
    }
    __syncthreads();

    // t = 0 init
    float mEa = 0.f, mLa = 0.f, mEb = 0.f, mLb = 0.f;
    int   ref = 0;
    if (slot == 0) { mEa = s_y[0][CNUM - 1]; mLa = s_y[0][ext_ca]; }

    if (lane >= VALID_L) {
        s_m[0][slot] = make_int4(__float_as_int(mEa), __float_as_int(mLa),
                                 __float_as_int(mEb), __float_as_int(mLb));
        s_r[0][slot] = ref;
    }
    __syncthreads();

    float fA = 1.f, fB = 1.f;
    auto boundary = [&](int par) {
        if (lane < HALO_L && slot >= 0) {
            int4 h = s_m[par][slot];
            mEa = __int_as_float(h.x); mLa = __int_as_float(h.y);
            mEb = __int_as_float(h.z); mLb = __int_as_float(h.w);
            ref = s_r[par][slot];
        }
        int fe = __float_as_int(fmaxf(fmaxf(mEa, mLa), fmaxf(mEb, mLb))) >> 23;
        int wm = ref + fe - 127;
        wm = max(wm, __shfl_up_sync(0xffffffffu, wm, 1));
        wm = max(wm, __shfl_up_sync(0xffffffffu, wm, 2));
        wm = max(wm, __shfl_up_sync(0xffffffffu, wm, 2));   // 6-lane window
        int refNew = wm + MARGIN;
        int dd = ref - refNew;
        int ddA = min(max(dd, -127), 127);
        float gA = pw2c(ddA), gB = pw2c(dd - ddA);
        mEa = (mEa * gA) * gB;  mLa = (mLa * gA) * gB;
        mEb = (mEb * gA) * gB;  mLb = (mLb * gA) * gB;
        ref = refNew;
        int r1 = __shfl_up_sync(0xffffffffu, ref, 1);
        int d  = min(r1 - ref, 127);
        int dA = min(max(d, -127), 127);
        fA = pw2c(dA);  fB = pw2c(d - dA);
    };

    int par = 0;
    int t0 = 1;
    for (; t0 + KST <= tend; t0 += KST, par ^= 1) {
        boundary(par);
        float pyB[KST], pyLa[KST], pyLb[KST], cB[KST], cLa[KST];
#pragma unroll
        for (int j = 0; j < KST; ++j) {
            const float* row = s_y[(t0 + j) & (RING - 1)];
            pyB[j]  = row[CNUM - 1];
            pyLa[j] = row[ext_ca];
            pyLb[j] = row[ext_cb];
            cB[j]   = (fA * pyB[j]) * fB;
            cLa[j]  = skipa ? (fA * pyLa[j]) * fB : 0.f;
        }
#pragma unroll
        for (int j = 0; j < KST; ++j) {
            float m1 = __shfl_up_sync(0xffffffffu, mLb, 1);
            float oEa = mEa, oLa = mLa, oEb = mEb, oLb = mLb;
            mEa = fmaf(m1, cB[j],  oEa * pyB[j]);
            mLa = fmaf(m1, cLa[j], (oLa + oEa) * pyLa[j]);
            mEb = (oEb + oLa) * pyB[j];
            mLb = fmaf(oLa, skb, oLb + oEb) * pyLb[j];
        }
        if (lane >= VALID_L) {
            s_m[par ^ 1][slot] = make_int4(__float_as_int(mEa), __float_as_int(mLa),
                                           __float_as_int(mEb), __float_as_int(mLb));
            s_r[par ^ 1][slot] = ref;
        }
        if (loader) {
#pragma unroll
            for (int jj = 0; jj < KST; ++jj) {
                int tn = t0 + PRO - 1 + jj;      // rows t0+25 .. t0+32
                if (tn < T) cp_async16(smy + (uint32_t)((tn & (RING - 1)) * CNUM + lane * 4) * 4,
                                       pb + (size_t)tn * CNUM + lane * 4);
                asm volatile("cp.async.commit_group;");
            }
            asm volatile("cp.async.wait_group 17;");
        }
        __syncthreads();
    }

    // tail (< 8 steps)
    if (t0 < tend) {
        boundary(par);
        for (int t = t0; t < tend; ++t) {
            const float* row = s_y[t & (RING - 1)];
            float pB = row[CNUM - 1], pLa = row[ext_ca], pLb = row[ext_cb];
            float cBt  = (fA * pB) * fB;
            float cLat = skipa ? (fA * pLa) * fB : 0.f;
            float m1 = __shfl_up_sync(0xffffffffu, mLb, 1);
            float oEa = mEa, oLa = mLa, oEb = mEb, oLb = mLb;
            mEa = fmaf(m1, cBt,  oEa * pB);
            mLa = fmaf(m1, cLat, (oLa + oEa) * pLa);
            mEb = (oEb + oLa) * pB;
            mLb = fmaf(oLa, skb, oLb + oEb) * pLb;
        }
    }

    // final publish (valid lanes): states 4*slot .. 4*slot+3
    if (lane >= HALO_L) {
        s_al[4 * slot + 0] = make_int2(__float_as_int(mEa), ref);
        s_al[4 * slot + 1] = make_int2(__float_as_int(mLa), ref);
        s_al[4 * slot + 2] = make_int2(__float_as_int(mEb), ref);
        s_al[4 * slot + 3] = make_int2(__float_as_int(mLb), ref);
    }
    __syncthreads();

    if (tid == 0) {
        int se = 2 * lab_len[b];
        int sp = (se > 0) ? (se - 1) : 0;
        int2 A = s_al[se];
        int2 P = s_al[sp];
        double va = (double)__int_as_float(A.x);
        double vp = (double)__int_as_float(P.x);
        long long ra = (va > 0.0) ? (long long)A.y : (long long)(-(1ll << 40));
        long long rp = (vp > 0.0) ? (long long)P.y : (long long)(-(1ll << 40));
        long long rm = (ra > rp) ? ra : rp;
        double sum = 0.0;
        if (va > 0.0) sum += va * exp2((double)(ra - rm));
        if (vp > 0.0) sum += vp * exp2((double)(rp - rm));
        out[b] = (float)(-(log(sum) + (double)rm * 0.6931471805599453));
    }
}

// ---------------------------------------------------------------------------
extern "C" void kernel_launch(void* const* d_in, const int* in_sizes, int n_in,
                              void* d_out, int out_size) {
    const float* y  = (const float*)d_in[0];
    const int*   yt = (const int*)d_in[1];
    const int*   il = (const int*)d_in[2];
    const int*   ll = (const int*)d_in[3];
    int B = in_sizes[2];
    int L = in_sizes[1] / B;
    int rows = in_sizes[0] / CNUM;   // B*T
    int T = rows / B;

    int sm_blocks = (rows * 32 + 255) / 256;
    softmax_kernel<<<sm_blocks, 256>>>(y, rows);
    ctc_kernel<<<B, NTH>>>(yt, il, ll, (float*)d_out, T, L);
}

// round 13
// speedup vs baseline: 1.7843x; 1.0079x over previous
#include <cuda_runtime.h>
#include <cstdint>
#include <math.h>

#define CNUM    128
#define SMAX    401
#define KST     10             // steps per barrier
#define HALO_L  5              // halo lanes (2 pairs each = 10 pairs = KST)
#define VALID_L 27
#define NW      4              // 4*27 lanes * 2 pairs = 216 pairs >= 202
#define NTH     (NW * 32)      // 128
#define NSLOT   (NW * VALID_L) // 108 slots (1 slot = 2 pairs = 4 states)
#define RING    64
#define MARGIN  20

// Scratch: softmax(y_pred) rows, [B][T][C] (64 MB).
__device__ float g_p[64 * 2000 * CNUM];

// ---------------------------------------------------------------------------
// Kernel 1: row softmax over C=128. One warp per (b,t) row.
// ---------------------------------------------------------------------------
__global__ void softmax_kernel(const float* __restrict__ y, int rows) {
    int gw   = (blockIdx.x * blockDim.x + threadIdx.x) >> 5;
    int lane = threadIdx.x & 31;
    if (gw >= rows) return;
    float4 v = reinterpret_cast<const float4*>(y)[(size_t)gw * 32 + lane];
    float m = fmaxf(fmaxf(v.x, v.y), fmaxf(v.z, v.w));
#pragma unroll
    for (int o = 16; o; o >>= 1) m = fmaxf(m, __shfl_xor_sync(0xffffffffu, m, o));
    float e0 = __expf(v.x - m), e1 = __expf(v.y - m);
    float e2 = __expf(v.z - m), e3 = __expf(v.w - m);
    float sm = e0 + e1 + e2 + e3;
#pragma unroll
    for (int o = 16; o; o >>= 1) sm += __shfl_xor_sync(0xffffffffu, sm, o);
    float inv = __frcp_rn(sm);
    reinterpret_cast<float4*>(g_p)[(size_t)gw * 32 + lane] =
        make_float4(e0 * inv, e1 * inv, e2 * inv, e3 * inv);
}

// ---------------------------------------------------------------------------
// Kernel 2: CTC alpha recursion, 2 pairs (4 states) per lane, block-scaled.
// Slot s = 27w + lane - 5 owns pairs (2s, 2s+1) = states 4s..4s+3
// (lanes 0..4 = halo mirroring prev warp's top 5 lanes; slot<0 stays zero).
// All 4 values share per-lane scale 2^ref, fixed for a 10-step block.
// Cross-lane: only pair-0's inputs -> 1 SHFL per step; dependence cycle
// spans 2 steps. Boundary: halo adopt -> 6-lane window max (24 states,
// flush-safe; growth 3^10 < 2^20 margin) -> two-factor rebase -> neighbor
// factor folded into per-block coefficients. Loading distributed across
// all 4 warps (per-warp commit groups, wait_group 2 ~ 2-block distance).
// ---------------------------------------------------------------------------
__device__ __forceinline__ void cp_async16(uint32_t saddr, const void* g) {
    asm volatile("cp.async.cg.shared.global [%0], [%1], 16;" :: "r"(saddr), "l"(g));
}
__device__ __forceinline__ float pw2c(int d) {   // exact 2^clamp(d,-127,127)
    return __int_as_float((min(max(d, -127), 127) + 127) << 23);
}

__global__ __launch_bounds__(NTH) void ctc_kernel(
    const int* __restrict__ labels, const int* __restrict__ in_len,
    const int* __restrict__ lab_len, float* __restrict__ out, int T, int L)
{
    __shared__ float s_y[RING][CNUM];     // 32 KB ring
    __shared__ int4  s_m[2][NSLOT];       // published mantissas (4 states)
    __shared__ int   s_r[2][NSLOT];       // published refs
    __shared__ int2  s_al[4 * NSLOT];     // final readout

    const int b    = blockIdx.x;
    const int tid  = threadIdx.x;
    const int wid  = tid >> 5;
    const int lane = tid & 31;
    const float* pb = g_p + (size_t)b * T * CNUM;
    const int tend  = min(T, in_len[b]);

    const int slot = wid * VALID_L + lane - HALO_L;
    const int q0 = 2 * slot, q1 = 2 * slot + 1;
    int  ext_ca = CNUM - 1, ext_cb = CNUM - 1;
    bool skipa = false, skipb = false;
    if (slot >= 0) {
        if (q0 < L) {
            int v = labels[b * L + q0];
            ext_ca = (v < 0) ? 0 : v;
            if (q0 >= 1) {
                int v2 = labels[b * L + q0 - 1];
                v2 = (v2 < 0) ? 0 : v2;
                skipa = (ext_ca != v2);
            }
        }
        if (q1 < L) {
            int v = labels[b * L + q1];
            ext_cb = (v < 0) ? 0 : v;
            int v2 = labels[b * L + q1 - 1];
            v2 = (v2 < 0) ? 0 : v2;
            skipb = (ext_cb != v2);
        }
    }
    const float skb = skipb ? 1.f : 0.f;

    uint32_t smy = (uint32_t)__cvta_generic_to_shared(&s_y[0][0]);

    // Distributed group issue: rows base+lo[wid] .. base+hi[wid] (10-row group).
    auto issue_group = [&](int base, int lo, int hi) {
        for (int r = lo; r <= hi; ++r) {
            int tn = base + r;
            if (tn < T) cp_async16(smy + (uint32_t)((tn & (RING - 1)) * CNUM + lane * 4) * 4,
                                   pb + (size_t)tn * CNUM + lane * 4);
        }
        asm volatile("cp.async.commit_group;");
    };
    const int glo = (wid == 0) ? 0 : (wid == 1) ? 3 : (wid == 2) ? 6 : 9;
    const int ghi = (wid == 0) ? 2 : (wid == 1) ? 5 : (wid == 2) ? 8 : 9;

    // Prologue: P1 rows 0..10 (w3 takes 9..10), P2 rows 11..20, P3 rows 21..30.
    // wait_group 2 -> P1 complete (rows 0..10).
    issue_group(0, glo, (wid == 3) ? 10 : ghi);
    issue_group(11, glo, ghi);
    issue_group(21, glo, ghi);
    asm volatile("cp.async.wait_group 2;");
    __syncthreads();

    // t = 0 init
    float mEa = 0.f, mLa = 0.f, mEb = 0.f, mLb = 0.f;
    int   ref = 0;
    if (slot == 0) { mEa = s_y[0][CNUM - 1]; mLa = s_y[0][ext_ca]; }

    if (lane >= VALID_L) {
        s_m[0][slot] = make_int4(__float_as_int(mEa), __float_as_int(mLa),
                                 __float_as_int(mEb), __float_as_int(mLb));
        s_r[0][slot] = ref;
    }
    __syncthreads();

    float fA = 1.f, fB = 1.f;
    auto boundary = [&](int par) {
        if (lane < HALO_L && slot >= 0) {
            int4 h = s_m[par][slot];
            mEa = __int_as_float(h.x); mLa = __int_as_float(h.y);
            mEb = __int_as_float(h.z); mLb = __int_as_float(h.w);
            ref = s_r[par][slot];
        }
        int fe = __float_as_int(fmaxf(fmaxf(mEa, mLa), fmaxf(mEb, mLb))) >> 23;
        int wm = ref + fe - 127;
        wm = max(wm, __shfl_up_sync(0xffffffffu, wm, 1));
        wm = max(wm, __shfl_up_sync(0xffffffffu, wm, 2));
        wm = max(wm, __shfl_up_sync(0xffffffffu, wm, 2));   // 6-lane window
        int refNew = wm + MARGIN;
        int dd = ref - refNew;
        int ddA = min(max(dd, -127), 127);
        float gA = pw2c(ddA), gB = pw2c(dd - ddA);
        mEa = (mEa * gA) * gB;  mLa = (mLa * gA) * gB;
        mEb = (mEb * gA) * gB;  mLb = (mLb * gA) * gB;
        ref = refNew;
        int r1 = __shfl_up_sync(0xffffffffu, ref, 1);
        int d  = min(r1 - ref, 127);
        int dA = min(max(d, -127), 127);
        fA = pw2c(dA);  fB = pw2c(d - dA);
    };

    int par = 0;
    int t0 = 1;
    for (; t0 + KST <= tend; t0 += KST, par ^= 1) {
        boundary(par);
        float pyB[KST], pyLa[KST], pyLb[KST], cB[KST], cLa[KST];
#pragma unroll
        for (int j = 0; j < KST; ++j) {
            const float* row = s_y[(t0 + j) & (RING - 1)];
            pyB[j]  = row[CNUM - 1];
            pyLa[j] = row[ext_ca];
            pyLb[j] = row[ext_cb];
            cB[j]   = (fA * pyB[j]) * fB;
            cLa[j]  = skipa ? (fA * pyLa[j]) * fB : 0.f;
        }
#pragma unroll
        for (int j = 0; j < KST; ++j) {
            float m1 = __shfl_up_sync(0xffffffffu, mLb, 1);
            float oEa = mEa, oLa = mLa, oEb = mEb, oLb = mLb;
            mEa = fmaf(m1, cB[j],  oEa * pyB[j]);
            mLa = fmaf(m1, cLa[j], (oLa + oEa) * pyLa[j]);
            mEb = (oEb + oLa) * pyB[j];
            mLb = fmaf(oLa, skb, oLb + oEb) * pyLb[j];
        }
        if (lane >= VALID_L) {
            s_m[par ^ 1][slot] = make_int4(__float_as_int(mEa), __float_as_int(mLa),
                                           __float_as_int(mEb), __float_as_int(mLb));
            s_r[par ^ 1][slot] = ref;
        }
        // prefetch rows t0+30 .. t0+39 (each warp its share, own group)
        issue_group(t0 + 30, glo, ghi);
        asm volatile("cp.async.wait_group 2;");
        __syncthreads();
    }

    // tail (< 10 steps; rows <= t0+9 guaranteed complete)
    if (t0 < tend) {
        boundary(par);
        for (int t = t0; t < tend; ++t) {
            const float* row = s_y[t & (RING - 1)];
            float pB = row[CNUM - 1], pLa = row[ext_ca], pLb = row[ext_cb];
            float cBt  = (fA * pB) * fB;
            float cLat = skipa ? (fA * pLa) * fB : 0.f;
            float m1 = __shfl_up_sync(0xffffffffu, mLb, 1);
            float oEa = mEa, oLa = mLa, oEb = mEb, oLb = mLb;
            mEa = fmaf(m1, cBt,  oEa * pB);
            mLa = fmaf(m1, cLat, (oLa + oEa) * pLa);
            mEb = (oEb + oLa) * pB;
            mLb = fmaf(oLa, skb, oLb + oEb) * pLb;
        }
    }

    // final publish (valid lanes): states 4*slot .. 4*slot+3
    if (lane >= HALO_L) {
        s_al[4 * slot + 0] = make_int2(__float_as_int(mEa), ref);
        s_al[4 * slot + 1] = make_int2(__float_as_int(mLa), ref);
        s_al[4 * slot + 2] = make_int2(__float_as_int(mEb), ref);
        s_al[4 * slot + 3] = make_int2(__float_as_int(mLb), ref);
    }
    __syncthreads();

    if (tid == 0) {
        int se = 2 * lab_len[b];
        int sp = (se > 0) ? (se - 1) : 0;
        int2 A = s_al[se];
        int2 P = s_al[sp];
        double va = (double)__int_as_float(A.x);
        double vp = (double)__int_as_float(P.x);
        long long ra = (va > 0.0) ? (long long)A.y : (long long)(-(1ll << 40));
        long long rp = (vp > 0.0) ? (long long)P.y : (long long)(-(1ll << 40));
        long long rm = (ra > rp) ? ra : rp;
        double sum = 0.0;
        if (va > 0.0) sum += va * exp2((double)(ra - rm));
        if (vp > 0.0) sum += vp * exp2((double)(rp - rm));
        out[b] = (float)(-(log(sum) + (double)rm * 0.6931471805599453));
    }
}

// ---------------------------------------------------------------------------
extern "C" void kernel_launch(void* const* d_in, const int* in_sizes, int n_in,
                              void* d_out, int out_size) {
    const float* y  = (const float*)d_in[0];
    const int*   yt = (const int*)d_in[1];
    const int*   il = (const int*)d_in[2];
    const int*   ll = (const int*)d_in[3];
    int B = in_sizes[2];
    int L = in_sizes[1] / B;
    int rows = in_sizes[0] / CNUM;   // B*T
    int T = rows / B;

    int sm_blocks = (rows * 32 + 255) / 256;
    softmax_kernel<<<sm_blocks, 256>>>(y, rows);
    ctc_kernel<<<B, NTH>>>(yt, il, ll, (float*)d_out, T, L);
}

// round 14
// speedup vs baseline: 1.8588x; 1.0418x over previous
#include <cuda_runtime.h>
#include <cstdint>
#include <math.h>

#define CNUM    128
#define SMAX    401
#define KST     8              // steps per barrier
#define HALO_L  2              // halo lanes (4 pairs each = 8 pair-hops = KST)
#define VALID_L 30
#define NW      2              // 2 warps * 30 lanes * 4 pairs = 240 pairs >= 202
#define NTH     (NW * 32)      // 64
#define NSLOT   (NW * VALID_L) // 60 slots (1 slot = 4 pairs = 8 states)
#define RING    64
#define MARGIN  20

// Scratch: softmax(y_pred) rows, [B][T][C] (64 MB).
__device__ float g_p[64 * 2000 * CNUM];

// ---------------------------------------------------------------------------
// Kernel 1: row softmax over C=128. One warp per (b,t) row. (unchanged)
// ---------------------------------------------------------------------------
__global__ void softmax_kernel(const float* __restrict__ y, int rows) {
    int gw   = (blockIdx.x * blockDim.x + threadIdx.x) >> 5;
    int lane = threadIdx.x & 31;
    if (gw >= rows) return;
    float4 v = reinterpret_cast<const float4*>(y)[(size_t)gw * 32 + lane];
    float m = fmaxf(fmaxf(v.x, v.y), fmaxf(v.z, v.w));
#pragma unroll
    for (int o = 16; o; o >>= 1) m = fmaxf(m, __shfl_xor_sync(0xffffffffu, m, o));
    float e0 = __expf(v.x - m), e1 = __expf(v.y - m);
    float e2 = __expf(v.z - m), e3 = __expf(v.w - m);
    float sm = e0 + e1 + e2 + e3;
#pragma unroll
    for (int o = 16; o; o >>= 1) sm += __shfl_xor_sync(0xffffffffu, sm, o);
    float inv = __frcp_rn(sm);
    reinterpret_cast<float4*>(g_p)[(size_t)gw * 32 + lane] =
        make_float4(e0 * inv, e1 * inv, e2 * inv, e3 * inv);
}

// ---------------------------------------------------------------------------
// Kernel 2: CTC alpha recursion, 4 pairs (8 states) per lane, 2 warps.
// Slot s = 30w + lane - 2 owns pairs 4s..4s+3 = states 8s..8s+7
// (warp1 lanes 0..1 = halo mirroring warp0 lanes 30..31; slot<0 lanes stay
// zero). All 8 values share per-lane scale 2^ref, fixed per 8-step block.
// Cross-lane: only pair0's input (prev lane's pair3 odd) -> 1 SHFL/step;
// pairs 1..3 chain in-registers, so the cross-lane dependence cycle spans
// 4 steps (SHFL latency amortized). Boundary: halo adopt (2 tiny LDS) ->
// 3-lane window max (24 states, R12-proven flush-safe; growth 3^8 < 2^20)
// -> two-factor rebase -> neighbor factor. One barrier per 8 steps.
// Softmax rows stream via cp.async (1 row per warp-instruction), ring 64,
// horizon t0+31, wait_group 2 (completed through t0+22).
// ---------------------------------------------------------------------------
__device__ __forceinline__ void cp_async16(uint32_t saddr, const void* g) {
    asm volatile("cp.async.cg.shared.global [%0], [%1], 16;" :: "r"(saddr), "l"(g));
}
__device__ __forceinline__ float pw2c(int d) {   // exact 2^clamp(d,-127,127)
    return __int_as_float((min(max(d, -127), 127) + 127) << 23);
}

__global__ __launch_bounds__(NTH) void ctc_kernel(
    const int* __restrict__ labels, const int* __restrict__ in_len,
    const int* __restrict__ lab_len, float* __restrict__ out, int T, int L)
{
    __shared__ float s_y[RING][CNUM];     // 32 KB ring
    __shared__ int4  s_hA[2][HALO_L], s_hB[2][HALO_L];  // halo publish
    __shared__ int   s_hr[2][HALO_L];
    __shared__ int2  s_al[8 * NSLOT];     // final readout (480 states)

    const int b    = blockIdx.x;
    const int tid  = threadIdx.x;
    const int wid  = tid >> 5;
    const int lane = tid & 31;
    const float* pb = g_p + (size_t)b * T * CNUM;
    const int tend  = min(T, in_len[b]);

    const int slot = wid * VALID_L + lane - HALO_L;

    // Per-pair classes and skip flags (pairs q = 4*slot + qi)
    int   exc0, exc1, exc2, exc3;
    float sk0 = 0.f, sk1 = 0.f, sk2 = 0.f, sk3 = 0.f;
    {
        int e[4]; float s[4];
#pragma unroll
        for (int qi = 0; qi < 4; ++qi) {
            int q = 4 * slot + qi;
            int c = CNUM - 1; float sf = 0.f;
            if (slot >= 0 && q >= 0 && q < L) {
                int v = labels[b * L + q];
                c = (v < 0) ? 0 : v;
                if (q >= 1) {
                    int v2 = labels[b * L + q - 1];
                    v2 = (v2 < 0) ? 0 : v2;
                    sf = (c != v2) ? 1.f : 0.f;
                }
            }
            e[qi] = c; s[qi] = sf;
        }
        exc0 = e[0]; exc1 = e[1]; exc2 = e[2]; exc3 = e[3];
        sk0 = s[0]; sk1 = s[1]; sk2 = s[2]; sk3 = s[3];
    }

    uint32_t smy = (uint32_t)__cvta_generic_to_shared(&s_y[0][0]);

    // One 8-row group per call: warp w loads rows base+4w .. base+4w+3
    // (each cp.async16 is warp-wide: 32 lanes x 16B = one 512B row).
    auto issue_group = [&](int base) {
#pragma unroll
        for (int r = 0; r < 4; ++r) {
            int tn = base + 4 * wid + r;
            if (tn < T) cp_async16(smy + (uint32_t)(((tn & (RING - 1)) * CNUM + lane * 4) * 4),
                                   pb + (size_t)tn * CNUM + lane * 4);
        }
        asm volatile("cp.async.commit_group;");
    };

    // Prologue: rows 0..31 in 4 groups; wait 2 -> rows 0..15 complete.
    issue_group(0); issue_group(8); issue_group(16); issue_group(24);
    asm volatile("cp.async.wait_group 2;");
    __syncthreads();

    // t = 0 init (slot 0 = warp0 lane 2)
    float mE0 = 0.f, mL0 = 0.f, mE1 = 0.f, mL1 = 0.f;
    float mE2 = 0.f, mL2 = 0.f, mE3 = 0.f, mL3 = 0.f;
    int   ref = 0;
    if (slot == 0) { mE0 = s_y[0][CNUM - 1]; mL0 = s_y[0][exc0]; }

    // initial halo publish (parity 0): warp0 lanes 30,31 -> slots 28,29
    if (wid == 0 && lane >= 32 - HALO_L) {
        int i = lane - (32 - HALO_L);
        s_hA[0][i] = make_int4(__float_as_int(mE0), __float_as_int(mL0),
                               __float_as_int(mE1), __float_as_int(mL1));
        s_hB[0][i] = make_int4(__float_as_int(mE2), __float_as_int(mL2),
                               __float_as_int(mE3), __float_as_int(mL3));
        s_hr[0][i] = ref;
    }
    __syncthreads();

    float fA = 1.f, fB = 1.f;
    auto boundary = [&](int par) {
        if (wid == 1 && lane < HALO_L) {
            int4 a = s_hA[par][lane], c = s_hB[par][lane];
            mE0 = __int_as_float(a.x); mL0 = __int_as_float(a.y);
            mE1 = __int_as_float(a.z); mL1 = __int_as_float(a.w);
            mE2 = __int_as_float(c.x); mL2 = __int_as_float(c.y);
            mE3 = __int_as_float(c.z); mL3 = __int_as_float(c.w);
            ref = s_hr[par][lane];
        }
        float fm = fmaxf(fmaxf(fmaxf(mE0, mL0), fmaxf(mE1, mL1)),
                         fmaxf(fmaxf(mE2, mL2), fmaxf(mE3, mL3)));
        int myexp = ref + ((__float_as_int(fm) >> 23) - 127);
        int s1 = __shfl_up_sync(0xffffffffu, myexp, 1);
        int s2 = __shfl_up_sync(0xffffffffu, myexp, 2);
        int wm = max(myexp, max(s1, s2));          // 3-lane window = 24 states
        int refNew = wm + MARGIN;
        int dd = ref - refNew;
        int ddA = min(max(dd, -127), 127);
        float gA = pw2c(ddA), gB = pw2c(dd - ddA);
        mE0 = (mE0 * gA) * gB;  mL0 = (mL0 * gA) * gB;
        mE1 = (mE1 * gA) * gB;  mL1 = (mL1 * gA) * gB;
        mE2 = (mE2 * gA) * gB;  mL2 = (mL2 * gA) * gB;
        mE3 = (mE3 * gA) * gB;  mL3 = (mL3 * gA) * gB;
        ref = refNew;
        int r1 = __shfl_up_sync(0xffffffffu, ref, 1);
        int d  = r1 - ref;
        int dA = min(max(d, -127), 127);
        fA = pw2c(dA);  fB = pw2c(d - dA);
    };

    int par = 0;
    int t0 = 1;
    for (; t0 + KST <= tend; t0 += KST, par ^= 1) {
        boundary(par);
#pragma unroll
        for (int j = 0; j < KST; ++j) {
            const float* row = s_y[(t0 + j) & (RING - 1)];
            float pB = row[CNUM - 1];
            float p0 = row[exc0], p1 = row[exc1], p2 = row[exc2], p3 = row[exc3];
            float m1 = __shfl_up_sync(0xffffffffu, mL3, 1);
            float in0 = (m1 * fA) * fB;
            float nE0 = (mE0 + in0) * pB;
            float nL0 = fmaf(in0, sk0, mL0 + mE0) * p0;
            float nE1 = (mE1 + mL0) * pB;
            float nL1 = fmaf(mL0, sk1, mL1 + mE1) * p1;
            float nE2 = (mE2 + mL1) * pB;
            float nL2 = fmaf(mL1, sk2, mL2 + mE2) * p2;
            float nE3 = (mE3 + mL2) * pB;
            float nL3 = fmaf(mL2, sk3, mL3 + mE3) * p3;
            mE0 = nE0; mL0 = nL0; mE1 = nE1; mL1 = nL1;
            mE2 = nE2; mL2 = nL2; mE3 = nE3; mL3 = nL3;
        }
        // publish halo for next block
        if (wid == 0 && lane >= 32 - HALO_L) {
            int i = lane - (32 - HALO_L);
            s_hA[par ^ 1][i] = make_int4(__float_as_int(mE0), __float_as_int(mL0),
                                         __float_as_int(mE1), __float_as_int(mL1));
            s_hB[par ^ 1][i] = make_int4(__float_as_int(mE2), __float_as_int(mL2),
                                         __float_as_int(mE3), __float_as_int(mL3));
            s_hr[par ^ 1][i] = ref;
        }
        issue_group(t0 + 31);                  // rows t0+31 .. t0+38
        asm volatile("cp.async.wait_group 2;");
        __syncthreads();
    }

    // tail (< 8 steps; rows through t0+22 complete)
    if (t0 < tend) {
        boundary(par);
        for (int t = t0; t < tend; ++t) {
            const float* row = s_y[t & (RING - 1)];
            float pB = row[CNUM - 1];
            float p0 = row[exc0], p1 = row[exc1], p2 = row[exc2], p3 = row[exc3];
            float m1 = __shfl_up_sync(0xffffffffu, mL3, 1);
            float in0 = (m1 * fA) * fB;
            float nE0 = (mE0 + in0) * pB;
            float nL0 = fmaf(in0, sk0, mL0 + mE0) * p0;
            float nE1 = (mE1 + mL0) * pB;
            float nL1 = fmaf(mL0, sk1, mL1 + mE1) * p1;
            float nE2 = (mE2 + mL1) * pB;
            float nL2 = fmaf(mL1, sk2, mL2 + mE2) * p2;
            float nE3 = (mE3 + mL2) * pB;
            float nL3 = fmaf(mL2, sk3, mL3 + mE3) * p3;
            mE0 = nE0; mL0 = nL0; mE1 = nE1; mL1 = nL1;
            mE2 = nE2; mL2 = nL2; mE3 = nE3; mL3 = nL3;
        }
    }

    // final publish (valid lanes): states 8*slot .. 8*slot+7
    if (lane >= HALO_L) {
        s_al[8 * slot + 0] = make_int2(__float_as_int(mE0), ref);
        s_al[8 * slot + 1] = make_int2(__float_as_int(mL0), ref);
        s_al[8 * slot + 2] = make_int2(__float_as_int(mE1), ref);
        s_al[8 * slot + 3] = make_int2(__float_as_int(mL1), ref);
        s_al[8 * slot + 4] = make_int2(__float_as_int(mE2), ref);
        s_al[8 * slot + 5] = make_int2(__float_as_int(mL2), ref);
        s_al[8 * slot + 6] = make_int2(__float_as_int(mE3), ref);
        s_al[8 * slot + 7] = make_int2(__float_as_int(mL3), ref);
    }
    __syncthreads();

    if (tid == 0) {
        int se = 2 * lab_len[b];
        int sp = (se > 0) ? (se - 1) : 0;
        int2 A = s_al[se];
        int2 P = s_al[sp];
        double va = (double)__int_as_float(A.x);
        double vp = (double)__int_as_float(P.x);
        long long ra = (va > 0.0) ? (long long)A.y : (long long)(-(1ll << 40));
        long long rp = (vp > 0.0) ? (long long)P.y : (long long)(-(1ll << 40));
        long long rm = (ra > rp) ? ra : rp;
        double sum = 0.0;
        if (va > 0.0) sum += va * exp2((double)(ra - rm));
        if (vp > 0.0) sum += vp * exp2((double)(rp - rm));
        out[b] = (float)(-(log(sum) + (double)rm * 0.6931471805599453));
    }
}

// ---------------------------------------------------------------------------
extern "C" void kernel_launch(void* const* d_in, const int* in_sizes, int n_in,
                              void* d_out, int out_size) {
    const float* y  = (const float*)d_in[0];
    const int*   yt = (const int*)d_in[1];
    const int*   il = (const int*)d_in[2];
    const int*   ll = (const int*)d_in[3];
    int B = in_sizes[2];
    int L = in_sizes[1] / B;
    int rows = in_sizes[0] / CNUM;   // B*T
    int T = rows / B;

    int sm_blocks = (rows * 32 + 255) / 256;
    softmax_kernel<<<sm_blocks, 256>>>(y, rows);
    ctc_kernel<<<B, NTH>>>(yt, il, ll, (float*)d_out, T, L);
}